// round 6
// baseline (speedup 1.0000x reference)
#include <cuda_runtime.h>
#include <cstdint>
#include <cstddef>

// ---------------- scratch (static __device__ arrays; no cudaMalloc) ----------------
static __device__ float  g_xchw[2 * 512 * 512];
static __device__ float  g_h1 [32 * 512 * 512];
static __device__ float  g_h2 [64 * 512 * 512];
static __device__ float  g_h2p[64 * 256 * 256];
static __device__ float  g_h3 [128 * 256 * 256];
static __device__ float  g_feat[128];
static __device__ float  g_u1[512];
static __device__ float  g_v1[512];
static __device__ float2 g_Ut[128 * 512];   // column-contiguous: [r][m]
static __device__ float2 g_Vt[128 * 512];

// ---------------- (H,W,2) -> CHW transpose ----------------
__global__ void prep_x_kernel(const float* __restrict__ x, float* __restrict__ xchw) {
    int idx = blockIdx.x * 256 + threadIdx.x;   // 512*512 exactly
    float2 v = reinterpret_cast<const float2*>(x)[idx];
    xchw[idx] = v.x;
    xchw[512 * 512 + idx] = v.y;
}

// ---------------- direct 3x3 conv (pad=1) + bias + ReLU ----------------
// block = 128 threads: og = tid>>6 (16 out-ch each), pg = tid&63 (4 px each)
// tile = 32 output channels x 256 pixels (one partial row)
template<int CIN>
__global__ __launch_bounds__(128)
void conv3x3_relu(const float* __restrict__ in, const float* __restrict__ wt,
                  const float* __restrict__ bias, float* __restrict__ out,
                  int H, int W) {
    extern __shared__ float sw[];               // 32 * CIN * 9 floats
    const int tid = threadIdx.x;
    const int obase = blockIdx.z * 32;
    for (int idx = tid; idx < 32 * CIN * 9; idx += 128)
        sw[idx] = wt[obase * CIN * 9 + idx];
    __syncthreads();

    const int og = tid >> 6;
    const int pg = tid & 63;
    const int h  = blockIdx.y;
    const int x0 = blockIdx.x * 256 + pg * 4;

    float acc[16][4];
#pragma unroll
    for (int a = 0; a < 16; ++a)
#pragma unroll
        for (int p = 0; p < 4; ++p) acc[a][p] = 0.f;

#pragma unroll 1
    for (int c = 0; c < CIN; ++c) {
#pragma unroll
        for (int ky = 0; ky < 3; ++ky) {
            const int y = h + ky - 1;
            const bool yv = ((unsigned)y < (unsigned)H);
            const float* ip = in + ((size_t)c * H + y) * W;
            float r[6];
#pragma unroll
            for (int dx = 0; dx < 6; ++dx) {
                int xx = x0 - 1 + dx;
                r[dx] = (yv && (unsigned)xx < (unsigned)W) ? __ldg(ip + xx) : 0.f;
            }
            const float* swp = sw + (og * 16) * (CIN * 9) + c * 9 + ky * 3;
#pragma unroll
            for (int kx = 0; kx < 3; ++kx) {
#pragma unroll
                for (int oo = 0; oo < 16; ++oo) {
                    float wv = swp[oo * (CIN * 9) + kx];   // warp-uniform -> LDS broadcast
                    acc[oo][0] = fmaf(wv, r[kx + 0], acc[oo][0]);
                    acc[oo][1] = fmaf(wv, r[kx + 1], acc[oo][1]);
                    acc[oo][2] = fmaf(wv, r[kx + 2], acc[oo][2]);
                    acc[oo][3] = fmaf(wv, r[kx + 3], acc[oo][3]);
                }
            }
        }
    }

#pragma unroll
    for (int oo = 0; oo < 16; ++oo) {
        const int o = obase + og * 16 + oo;
        const float b = bias[o];
        float* op = out + ((size_t)o * H + h) * W + x0;
#pragma unroll
        for (int p = 0; p < 4; ++p)
            op[p] = fmaxf(acc[oo][p] + b, 0.f);
    }
}

// ---------------- 2x2 maxpool stride 2 (64ch, 512 -> 256) ----------------
__global__ void maxpool2_kernel(const float* __restrict__ in, float* __restrict__ out) {
    int idx = blockIdx.x * 256 + threadIdx.x;   // 64*256*256 exactly
    int x = idx & 255, y = (idx >> 8) & 255, c = idx >> 16;
    const float* p = in + ((size_t)c * 512 + 2 * y) * 512 + 2 * x;
    out[idx] = fmaxf(fmaxf(p[0], p[1]), fmaxf(p[512], p[513]));
}

// ---------------- global average pool: 128 channels of 256x256 ----------------
__global__ void avgpool_kernel(const float* __restrict__ in, float* __restrict__ feat) {
    const int c = blockIdx.x;
    const float* p = in + (size_t)c * 65536;
    float s = 0.f;
    for (int i = threadIdx.x; i < 65536; i += 256) s += p[i];
    __shared__ float sh[256];
    sh[threadIdx.x] = s;
    __syncthreads();
    for (int off = 128; off > 0; off >>= 1) {
        if (threadIdx.x < off) sh[threadIdx.x] += sh[threadIdx.x + off];
        __syncthreads();
    }
    if (threadIdx.x == 0) feat[c] = sh[0] * (1.f / 65536.f);
}

// ---------------- fused small FC trunk + s head (softplus+sort) + u1/v1 ----------------
__device__ __forceinline__ float dot4(const float* __restrict__ w,
                                      const float* __restrict__ v, int n4) {
    float a = 0.f;
    const float4* w4 = (const float4*)w;
    const float4* v4 = (const float4*)v;
#pragma unroll 8
    for (int k = 0; k < n4; ++k) {
        float4 ww = w4[k], vv = v4[k];
        a += ww.x * vv.x + ww.y * vv.y + ww.z * vv.z + ww.w * vv.w;
    }
    return a;
}

__global__ __launch_bounds__(512)
void small_layers_kernel(const float* __restrict__ feat,
    const float* __restrict__ fw1, const float* __restrict__ fb1,
    const float* __restrict__ fw2, const float* __restrict__ fb2,
    const float* __restrict__ sw1, const float* __restrict__ sb1,
    const float* __restrict__ sw2, const float* __restrict__ sb2,
    const float* __restrict__ uw1, const float* __restrict__ ub1,
    const float* __restrict__ vw1, const float* __restrict__ vb1,
    float* __restrict__ u1g, float* __restrict__ v1g, float* __restrict__ s_out) {
    __shared__ __align__(16) float sf[128];
    __shared__ __align__(16) float f1[256];
    __shared__ __align__(16) float f2[512];
    __shared__ __align__(16) float s1[256];
    __shared__ float sv[128];
    const int t = threadIdx.x;

    if (t < 128) sf[t] = feat[t];
    __syncthreads();

    if (t < 256) f1[t] = fmaxf(fb1[t] + dot4(fw1 + t * 128, sf, 32), 0.f);
    __syncthreads();

    f2[t] = fmaxf(fb2[t] + dot4(fw2 + t * 256, f1, 64), 0.f);
    __syncthreads();

    if (t < 256) s1[t] = fmaxf(sb1[t] + dot4(sw1 + (size_t)t * 512, f2, 128), 0.f);
    __syncthreads();

    if (t < 128) {
        float xv = sb2[t] + dot4(sw2 + t * 256, s1, 64);
        sv[t] = (xv > 0.f) ? (xv + log1pf(expf(-xv))) : log1pf(expf(xv));
    }
    __syncthreads();

    // descending sort by rank (ties: later original index first, matching sort+reverse)
    if (t < 128) {
        float v = sv[t];
        int rank = 0;
        for (int j = 0; j < 128; ++j) {
            float o = sv[j];
            rank += (o > v) || (o == v && j > t);
        }
        s_out[rank] = v;
    }

    u1g[t] = fmaxf(ub1[t] + dot4(uw1 + (size_t)t * 512, f2, 128), 0.f);
    v1g[t] = fmaxf(vb1[t] + dot4(vw1 + (size_t)t * 512, f2, 128), 0.f);
}

// ---------------- big head matvecs: 2 x (131072 x 512), write transposed ----------------
__global__ __launch_bounds__(256)
void big_head_kernel(const float* __restrict__ uw2, const float* __restrict__ ub2,
                     const float* __restrict__ vw2, const float* __restrict__ vb2,
                     const float* __restrict__ u1, const float* __restrict__ v1,
                     float* __restrict__ Ut, float* __restrict__ Vt) {
    __shared__ __align__(16) float su[512];
    __shared__ __align__(16) float svv[512];
    const int t = threadIdx.x;
    for (int i = t; i < 512; i += 256) { su[i] = u1[i]; svv[i] = v1[i]; }
    __syncthreads();

    const int lane = t & 31, warp = t >> 5;
    const int gw = blockIdx.x * 8 + warp;           // 16384 warps total
#pragma unroll 1
    for (int rr = 0; rr < 16; ++rr) {
        int e = gw * 16 + rr;                       // 0..262143
        const float* wrow; const float* xv; float b; float* dst;
        if (e < 131072) {
            wrow = uw2 + (size_t)e * 512; xv = su; b = ub2[e];
            int m = e >> 8, r = (e >> 1) & 127, cp = e & 1;
            dst = Ut + (size_t)(r * 512 + m) * 2 + cp;
        } else {
            int e2 = e - 131072;
            wrow = vw2 + (size_t)e2 * 512; xv = svv; b = vb2[e2];
            int m = e2 >> 8, r = (e2 >> 1) & 127, cp = e2 & 1;
            dst = Vt + (size_t)(r * 512 + m) * 2 + cp;
        }
        float a = 0.f;
        const float4* w4 = (const float4*)wrow;
        const float4* x4 = (const float4*)xv;
#pragma unroll
        for (int k = lane; k < 128; k += 32) {
            float4 ww = w4[k], vv = x4[k];
            a += ww.x * vv.x + ww.y * vv.y + ww.z * vv.z + ww.w * vv.w;
        }
#pragma unroll
        for (int off = 16; off; off >>= 1) a += __shfl_down_sync(0xffffffffu, a, off);
        if (lane == 0) *dst = a + b;
    }
}

// ---------------- right-looking modified Gram-Schmidt (== reference MGS per column) ----
// block 0: U, block 1: V. 1024 threads. Matrix is column-contiguous float2[128][512].
__global__ __launch_bounds__(1024)
void gs_kernel(float2* __restrict__ Ut, float2* __restrict__ Vt, float* __restrict__ out) {
    float2* Vm = (blockIdx.x == 0) ? Ut : Vt;
    float* outp = out + ((blockIdx.x == 0) ? 0 : (131072 + 128));
    __shared__ float2 q[512];
    __shared__ float red[32];
    __shared__ float s_inv;
    const int t = threadIdx.x;
    const int lane = t & 31, warp = t >> 5;

#pragma unroll 1
    for (int i = 0; i < 128; ++i) {
        // ---- normalize column i ----
        float2 v = make_float2(0.f, 0.f);
        float nr = 0.f;
        if (t < 512) {
            v = Vm[i * 512 + t];
            nr = v.x * v.x + v.y * v.y;
        }
#pragma unroll
        for (int off = 16; off; off >>= 1) nr += __shfl_down_sync(0xffffffffu, nr, off);
        if (lane == 0) red[warp] = nr;
        __syncthreads();
        if (warp == 0) {
            float s = red[lane];
#pragma unroll
            for (int off = 16; off; off >>= 1) s += __shfl_down_sync(0xffffffffu, s, off);
            if (lane == 0) s_inv = 1.f / sqrtf(s + 1e-8f);
        }
        __syncthreads();
        if (t < 512) {
            float inv = s_inv;
            float2 qv = make_float2(v.x * inv, v.y * inv);
            q[t] = qv;
            // column i is final: emit in (m, r, 2) layout
            outp[t * 256 + i * 2 + 0] = qv.x;
            outp[t * 256 + i * 2 + 1] = qv.y;
        }
        __syncthreads();

        // ---- rank-1 update of columns j > i (one column per warp, strided) ----
        for (int j = i + 1 + warp; j < 128; j += 32) {
            float2* col = Vm + j * 512;
            float cr = 0.f, ci = 0.f;
#pragma unroll
            for (int k = 0; k < 16; ++k) {
                int m = lane + 32 * k;
                float2 vm = col[m];
                float2 qm = q[m];
                cr += qm.x * vm.x + qm.y * vm.y;     // conj(q) * v
                ci += qm.x * vm.y - qm.y * vm.x;
            }
#pragma unroll
            for (int off = 16; off; off >>= 1) {
                cr += __shfl_xor_sync(0xffffffffu, cr, off);
                ci += __shfl_xor_sync(0xffffffffu, ci, off);
            }
#pragma unroll
            for (int k = 0; k < 16; ++k) {
                int m = lane + 32 * k;
                float2 vm = col[m];                   // L1 hit (just read above)
                float2 qm = q[m];
                vm.x -= cr * qm.x - ci * qm.y;
                vm.y -= cr * qm.y + ci * qm.x;
                col[m] = vm;
            }
        }
        __syncthreads();
    }
}

// ---------------- launch ----------------
extern "C" void kernel_launch(void* const* d_in, const int* in_sizes, int n_in,
                              void* d_out, int out_size) {
    const float* x   = (const float*)d_in[0];
    const float* cw1 = (const float*)d_in[1];  const float* cb1 = (const float*)d_in[2];
    const float* cw2 = (const float*)d_in[3];  const float* cb2 = (const float*)d_in[4];
    const float* cw3 = (const float*)d_in[5];  const float* cb3 = (const float*)d_in[6];
    const float* fw1 = (const float*)d_in[7];  const float* fb1 = (const float*)d_in[8];
    const float* fw2 = (const float*)d_in[9];  const float* fb2 = (const float*)d_in[10];
    const float* sw1 = (const float*)d_in[11]; const float* sb1 = (const float*)d_in[12];
    const float* sw2 = (const float*)d_in[13]; const float* sb2 = (const float*)d_in[14];
    const float* uw1 = (const float*)d_in[15]; const float* ub1 = (const float*)d_in[16];
    const float* uw2 = (const float*)d_in[17]; const float* ub2 = (const float*)d_in[18];
    const float* vw1 = (const float*)d_in[19]; const float* vb1 = (const float*)d_in[20];
    const float* vw2 = (const float*)d_in[21]; const float* vb2 = (const float*)d_in[22];
    float* out = (float*)d_out;

    float *xchw, *h1, *h2, *h2p, *h3, *feat, *u1, *v1;
    float2 *Ut, *Vt;
    cudaGetSymbolAddress((void**)&xchw, g_xchw);
    cudaGetSymbolAddress((void**)&h1,   g_h1);
    cudaGetSymbolAddress((void**)&h2,   g_h2);
    cudaGetSymbolAddress((void**)&h2p,  g_h2p);
    cudaGetSymbolAddress((void**)&h3,   g_h3);
    cudaGetSymbolAddress((void**)&feat, g_feat);
    cudaGetSymbolAddress((void**)&u1,   g_u1);
    cudaGetSymbolAddress((void**)&v1,   g_v1);
    cudaGetSymbolAddress((void**)&Ut,   g_Ut);
    cudaGetSymbolAddress((void**)&Vt,   g_Vt);

    // conv3 needs 72 KB dynamic smem (> 48 KB default)
    cudaFuncSetAttribute(conv3x3_relu<64>, cudaFuncAttributeMaxDynamicSharedMemorySize,
                         32 * 64 * 9 * 4);

    prep_x_kernel<<<1024, 256>>>(x, xchw);
    conv3x3_relu<2> <<<dim3(2, 512, 1), 128, 32 * 2  * 9 * 4>>>(xchw, cw1, cb1, h1, 512, 512);
    conv3x3_relu<32><<<dim3(2, 512, 2), 128, 32 * 32 * 9 * 4>>>(h1,   cw2, cb2, h2, 512, 512);
    maxpool2_kernel<<<16384, 256>>>(h2, h2p);
    conv3x3_relu<64><<<dim3(1, 256, 4), 128, 32 * 64 * 9 * 4>>>(h2p,  cw3, cb3, h3, 256, 256);
    avgpool_kernel<<<128, 256>>>(h3, feat);
    small_layers_kernel<<<1, 512>>>(feat, fw1, fb1, fw2, fb2, sw1, sb1, sw2, sb2,
                                    uw1, ub1, vw1, vb1, u1, v1, out + 131072);
    big_head_kernel<<<2048, 256>>>(uw2, ub2, vw2, vb2, u1, v1, (float*)Ut, (float*)Vt);
    gs_kernel<<<2, 1024>>>(Ut, Vt, out);
}

// round 7
// speedup vs baseline: 1.0068x; 1.0068x over previous
#include <cuda_runtime.h>
#include <cstdint>
#include <cstddef>

// ---------------- scratch (static __device__ arrays; no cudaMalloc) ----------------
static __device__ float  g_xchw[2 * 512 * 512];
static __device__ float  g_h1 [32 * 512 * 512];
static __device__ float  g_h2 [64 * 512 * 512];
static __device__ float  g_h2p[64 * 256 * 256];
static __device__ float  g_h3 [128 * 256 * 256];
static __device__ float  g_feat[128];
static __device__ float  g_u1[512];
static __device__ float  g_v1[512];
static __device__ float2 g_Ut[128 * 512];   // column-contiguous: [r][m]
static __device__ float2 g_Vt[128 * 512];

// ---------------- (H,W,2) -> CHW transpose ----------------
__global__ void prep_x_kernel(const float* __restrict__ x, float* __restrict__ xchw) {
    int idx = blockIdx.x * 256 + threadIdx.x;   // 512*512 exactly
    float2 v = reinterpret_cast<const float2*>(x)[idx];
    xchw[idx] = v.x;
    xchw[512 * 512 + idx] = v.y;
}

// ---------------- direct 3x3 conv (pad=1) + bias + ReLU ----------------
// block = 128 threads: og = tid>>6 (16 out-ch each), pg = tid&63 (4 px each)
// tile = 32 output channels x 256 pixels (one partial row)
template<int CIN>
__global__ __launch_bounds__(128)
void conv3x3_relu(const float* __restrict__ in, const float* __restrict__ wt,
                  const float* __restrict__ bias, float* __restrict__ out,
                  int H, int W) {
    extern __shared__ float sw[];               // 32 * CIN * 9 floats
    const int tid = threadIdx.x;
    const int obase = blockIdx.z * 32;
    for (int idx = tid; idx < 32 * CIN * 9; idx += 128)
        sw[idx] = wt[obase * CIN * 9 + idx];
    __syncthreads();

    const int og = tid >> 6;
    const int pg = tid & 63;
    const int h  = blockIdx.y;
    const int x0 = blockIdx.x * 256 + pg * 4;

    float acc[16][4];
#pragma unroll
    for (int a = 0; a < 16; ++a)
#pragma unroll
        for (int p = 0; p < 4; ++p) acc[a][p] = 0.f;

#pragma unroll 1
    for (int c = 0; c < CIN; ++c) {
#pragma unroll
        for (int ky = 0; ky < 3; ++ky) {
            const int y = h + ky - 1;
            const bool yv = ((unsigned)y < (unsigned)H);
            const float* ip = in + ((size_t)c * H + y) * W;
            float r[6];
#pragma unroll
            for (int dx = 0; dx < 6; ++dx) {
                int xx = x0 - 1 + dx;
                r[dx] = (yv && (unsigned)xx < (unsigned)W) ? __ldg(ip + xx) : 0.f;
            }
            const float* swp = sw + (og * 16) * (CIN * 9) + c * 9 + ky * 3;
#pragma unroll
            for (int kx = 0; kx < 3; ++kx) {
#pragma unroll
                for (int oo = 0; oo < 16; ++oo) {
                    float wv = swp[oo * (CIN * 9) + kx];   // warp-uniform -> LDS broadcast
                    acc[oo][0] = fmaf(wv, r[kx + 0], acc[oo][0]);
                    acc[oo][1] = fmaf(wv, r[kx + 1], acc[oo][1]);
                    acc[oo][2] = fmaf(wv, r[kx + 2], acc[oo][2]);
                    acc[oo][3] = fmaf(wv, r[kx + 3], acc[oo][3]);
                }
            }
        }
    }

#pragma unroll
    for (int oo = 0; oo < 16; ++oo) {
        const int o = obase + og * 16 + oo;
        const float b = bias[o];
        float* op = out + ((size_t)o * H + h) * W + x0;
#pragma unroll
        for (int p = 0; p < 4; ++p)
            op[p] = fmaxf(acc[oo][p] + b, 0.f);
    }
}

// ---------------- 2x2 maxpool stride 2 (64ch, 512 -> 256) ----------------
__global__ void maxpool2_kernel(const float* __restrict__ in, float* __restrict__ out) {
    int idx = blockIdx.x * 256 + threadIdx.x;   // 64*256*256 exactly
    int x = idx & 255, y = (idx >> 8) & 255, c = idx >> 16;
    const float* p = in + ((size_t)c * 512 + 2 * y) * 512 + 2 * x;
    out[idx] = fmaxf(fmaxf(p[0], p[1]), fmaxf(p[512], p[513]));
}

// ---------------- global average pool: 128 channels of 256x256 ----------------
__global__ void avgpool_kernel(const float* __restrict__ in, float* __restrict__ feat) {
    const int c = blockIdx.x;
    const float* p = in + (size_t)c * 65536;
    float s = 0.f;
    for (int i = threadIdx.x; i < 65536; i += 256) s += p[i];
    __shared__ float sh[256];
    sh[threadIdx.x] = s;
    __syncthreads();
    for (int off = 128; off > 0; off >>= 1) {
        if (threadIdx.x < off) sh[threadIdx.x] += sh[threadIdx.x + off];
        __syncthreads();
    }
    if (threadIdx.x == 0) feat[c] = sh[0] * (1.f / 65536.f);
}

// ---------------- fused small FC trunk + s head (softplus+sort) + u1/v1 ----------------
__device__ __forceinline__ float dot4(const float* __restrict__ w,
                                      const float* __restrict__ v, int n4) {
    float a = 0.f;
    const float4* w4 = (const float4*)w;
    const float4* v4 = (const float4*)v;
#pragma unroll 8
    for (int k = 0; k < n4; ++k) {
        float4 ww = w4[k], vv = v4[k];
        a += ww.x * vv.x + ww.y * vv.y + ww.z * vv.z + ww.w * vv.w;
    }
    return a;
}

__global__ __launch_bounds__(512)
void small_layers_kernel(const float* __restrict__ feat,
    const float* __restrict__ fw1, const float* __restrict__ fb1,
    const float* __restrict__ fw2, const float* __restrict__ fb2,
    const float* __restrict__ sw1, const float* __restrict__ sb1,
    const float* __restrict__ sw2, const float* __restrict__ sb2,
    const float* __restrict__ uw1, const float* __restrict__ ub1,
    const float* __restrict__ vw1, const float* __restrict__ vb1,
    float* __restrict__ u1g, float* __restrict__ v1g, float* __restrict__ s_out) {
    __shared__ __align__(16) float sf[128];
    __shared__ __align__(16) float f1[256];
    __shared__ __align__(16) float f2[512];
    __shared__ __align__(16) float s1[256];
    __shared__ float sv[128];
    const int t = threadIdx.x;

    if (t < 128) sf[t] = feat[t];
    __syncthreads();

    if (t < 256) f1[t] = fmaxf(fb1[t] + dot4(fw1 + t * 128, sf, 32), 0.f);
    __syncthreads();

    f2[t] = fmaxf(fb2[t] + dot4(fw2 + t * 256, f1, 64), 0.f);
    __syncthreads();

    if (t < 256) s1[t] = fmaxf(sb1[t] + dot4(sw1 + (size_t)t * 512, f2, 128), 0.f);
    __syncthreads();

    if (t < 128) {
        float xv = sb2[t] + dot4(sw2 + t * 256, s1, 64);
        sv[t] = (xv > 0.f) ? (xv + log1pf(expf(-xv))) : log1pf(expf(xv));
    }
    __syncthreads();

    // descending sort by rank (ties: later original index first, matching sort+reverse)
    if (t < 128) {
        float v = sv[t];
        int rank = 0;
        for (int j = 0; j < 128; ++j) {
            float o = sv[j];
            rank += (o > v) || (o == v && j > t);
        }
        s_out[rank] = v;
    }

    u1g[t] = fmaxf(ub1[t] + dot4(uw1 + (size_t)t * 512, f2, 128), 0.f);
    v1g[t] = fmaxf(vb1[t] + dot4(vw1 + (size_t)t * 512, f2, 128), 0.f);
}

// ---------------- big head matvecs: 2 x (131072 x 512), write transposed ----------------
__global__ __launch_bounds__(256)
void big_head_kernel(const float* __restrict__ uw2, const float* __restrict__ ub2,
                     const float* __restrict__ vw2, const float* __restrict__ vb2,
                     const float* __restrict__ u1, const float* __restrict__ v1,
                     float* __restrict__ Ut, float* __restrict__ Vt) {
    __shared__ __align__(16) float su[512];
    __shared__ __align__(16) float svv[512];
    const int t = threadIdx.x;
    for (int i = t; i < 512; i += 256) { su[i] = u1[i]; svv[i] = v1[i]; }
    __syncthreads();

    const int lane = t & 31, warp = t >> 5;
    const int gw = blockIdx.x * 8 + warp;           // 16384 warps total
#pragma unroll 1
    for (int rr = 0; rr < 16; ++rr) {
        int e = gw * 16 + rr;                       // 0..262143
        const float* wrow; const float* xv; float b; float* dst;
        if (e < 131072) {
            wrow = uw2 + (size_t)e * 512; xv = su; b = ub2[e];
            int m = e >> 8, r = (e >> 1) & 127, cp = e & 1;
            dst = Ut + (size_t)(r * 512 + m) * 2 + cp;
        } else {
            int e2 = e - 131072;
            wrow = vw2 + (size_t)e2 * 512; xv = svv; b = vb2[e2];
            int m = e2 >> 8, r = (e2 >> 1) & 127, cp = e2 & 1;
            dst = Vt + (size_t)(r * 512 + m) * 2 + cp;
        }
        float a = 0.f;
        const float4* w4 = (const float4*)wrow;
        const float4* x4 = (const float4*)xv;
#pragma unroll
        for (int k = lane; k < 128; k += 32) {
            float4 ww = w4[k], vv = x4[k];
            a += ww.x * vv.x + ww.y * vv.y + ww.z * vv.z + ww.w * vv.w;
        }
#pragma unroll
        for (int off = 16; off; off >>= 1) a += __shfl_down_sync(0xffffffffu, a, off);
        if (lane == 0) *dst = a + b;
    }
}

// ---------------- right-looking modified Gram-Schmidt (== reference MGS per column) ----
// block 0: U, block 1: V. 1024 threads. Matrix is column-contiguous float2[128][512].
__global__ __launch_bounds__(1024)
void gs_kernel(float2* __restrict__ Ut, float2* __restrict__ Vt, float* __restrict__ out) {
    float2* Vm = (blockIdx.x == 0) ? Ut : Vt;
    float* outp = out + ((blockIdx.x == 0) ? 0 : (131072 + 128));
    __shared__ float2 q[512];
    __shared__ float red[32];
    __shared__ float s_inv;
    const int t = threadIdx.x;
    const int lane = t & 31, warp = t >> 5;

#pragma unroll 1
    for (int i = 0; i < 128; ++i) {
        // ---- normalize column i ----
        float2 v = make_float2(0.f, 0.f);
        float nr = 0.f;
        if (t < 512) {
            v = Vm[i * 512 + t];
            nr = v.x * v.x + v.y * v.y;
        }
#pragma unroll
        for (int off = 16; off; off >>= 1) nr += __shfl_down_sync(0xffffffffu, nr, off);
        if (lane == 0) red[warp] = nr;
        __syncthreads();
        if (warp == 0) {
            float s = red[lane];
#pragma unroll
            for (int off = 16; off; off >>= 1) s += __shfl_down_sync(0xffffffffu, s, off);
            if (lane == 0) s_inv = 1.f / sqrtf(s + 1e-8f);
        }
        __syncthreads();
        if (t < 512) {
            float inv = s_inv;
            float2 qv = make_float2(v.x * inv, v.y * inv);
            q[t] = qv;
            // column i is final: emit in (m, r, 2) layout
            outp[t * 256 + i * 2 + 0] = qv.x;
            outp[t * 256 + i * 2 + 1] = qv.y;
        }
        __syncthreads();

        // ---- rank-1 update of columns j > i (one column per warp, strided) ----
        for (int j = i + 1 + warp; j < 128; j += 32) {
            float2* col = Vm + j * 512;
            float cr = 0.f, ci = 0.f;
#pragma unroll
            for (int k = 0; k < 16; ++k) {
                int m = lane + 32 * k;
                float2 vm = col[m];
                float2 qm = q[m];
                cr += qm.x * vm.x + qm.y * vm.y;     // conj(q) * v
                ci += qm.x * vm.y - qm.y * vm.x;
            }
#pragma unroll
            for (int off = 16; off; off >>= 1) {
                cr += __shfl_xor_sync(0xffffffffu, cr, off);
                ci += __shfl_xor_sync(0xffffffffu, ci, off);
            }
#pragma unroll
            for (int k = 0; k < 16; ++k) {
                int m = lane + 32 * k;
                float2 vm = col[m];                   // L1 hit (just read above)
                float2 qm = q[m];
                vm.x -= cr * qm.x - ci * qm.y;
                vm.y -= cr * qm.y + ci * qm.x;
                col[m] = vm;
            }
        }
        __syncthreads();
    }
}

// ---------------- launch ----------------
extern "C" void kernel_launch(void* const* d_in, const int* in_sizes, int n_in,
                              void* d_out, int out_size) {
    const float* x   = (const float*)d_in[0];
    const float* cw1 = (const float*)d_in[1];  const float* cb1 = (const float*)d_in[2];
    const float* cw2 = (const float*)d_in[3];  const float* cb2 = (const float*)d_in[4];
    const float* cw3 = (const float*)d_in[5];  const float* cb3 = (const float*)d_in[6];
    const float* fw1 = (const float*)d_in[7];  const float* fb1 = (const float*)d_in[8];
    const float* fw2 = (const float*)d_in[9];  const float* fb2 = (const float*)d_in[10];
    const float* sw1 = (const float*)d_in[11]; const float* sb1 = (const float*)d_in[12];
    const float* sw2 = (const float*)d_in[13]; const float* sb2 = (const float*)d_in[14];
    const float* uw1 = (const float*)d_in[15]; const float* ub1 = (const float*)d_in[16];
    const float* uw2 = (const float*)d_in[17]; const float* ub2 = (const float*)d_in[18];
    const float* vw1 = (const float*)d_in[19]; const float* vb1 = (const float*)d_in[20];
    const float* vw2 = (const float*)d_in[21]; const float* vb2 = (const float*)d_in[22];
    float* out = (float*)d_out;

    float *xchw, *h1, *h2, *h2p, *h3, *feat, *u1, *v1;
    float2 *Ut, *Vt;
    cudaGetSymbolAddress((void**)&xchw, g_xchw);
    cudaGetSymbolAddress((void**)&h1,   g_h1);
    cudaGetSymbolAddress((void**)&h2,   g_h2);
    cudaGetSymbolAddress((void**)&h2p,  g_h2p);
    cudaGetSymbolAddress((void**)&h3,   g_h3);
    cudaGetSymbolAddress((void**)&feat, g_feat);
    cudaGetSymbolAddress((void**)&u1,   g_u1);
    cudaGetSymbolAddress((void**)&v1,   g_v1);
    cudaGetSymbolAddress((void**)&Ut,   g_Ut);
    cudaGetSymbolAddress((void**)&Vt,   g_Vt);

    // conv3 needs 72 KB dynamic smem (> 48 KB default)
    cudaFuncSetAttribute(conv3x3_relu<64>, cudaFuncAttributeMaxDynamicSharedMemorySize,
                         32 * 64 * 9 * 4);

    prep_x_kernel<<<1024, 256>>>(x, xchw);
    conv3x3_relu<2> <<<dim3(2, 512, 1), 128, 32 * 2  * 9 * 4>>>(xchw, cw1, cb1, h1, 512, 512);
    conv3x3_relu<32><<<dim3(2, 512, 2), 128, 32 * 32 * 9 * 4>>>(h1,   cw2, cb2, h2, 512, 512);
    maxpool2_kernel<<<16384, 256>>>(h2, h2p);
    conv3x3_relu<64><<<dim3(1, 256, 4), 128, 32 * 64 * 9 * 4>>>(h2p,  cw3, cb3, h3, 256, 256);
    avgpool_kernel<<<128, 256>>>(h3, feat);
    small_layers_kernel<<<1, 512>>>(feat, fw1, fb1, fw2, fb2, sw1, sb1, sw2, sb2,
                                    uw1, ub1, vw1, vb1, u1, v1, out + 131072);
    big_head_kernel<<<2048, 256>>>(uw2, ub2, vw2, vb2, u1, v1, (float*)Ut, (float*)Vt);
    gs_kernel<<<2, 1024>>>(Ut, Vt, out);
}